// round 13
// baseline (speedup 1.0000x reference)
#include <cuda_runtime.h>
#include <cuda_bf16.h>
#include <cstdint>

// ---------------- problem constants ----------------
#define NB_MAX   2048
#define NE       8
#define NA       6
#define TB       32

// ---------------- scratch (device globals; no allocs allowed) ----------------
// All activations stored as uint2 {bf16x2_hi, bf16x2_lo} pairs.
// g_x0: conv1 input, planar [b][c][h][w/2]
__device__ uint2 g_x0[(size_t)NB_MAX * 3 * 84 * 42];
// position-major [b*pos][c/2]
__device__ uint2 g_x1[(size_t)NB_MAX * 400 * 16];
__device__ uint2 g_x2[(size_t)NB_MAX * 81 * 32];
__device__ uint2 g_x3[(size_t)NB_MAX * 49 * 32];
__device__ float g_h1[(size_t)NB_MAX * 64];
__device__ int   g_cnt[NE];
__device__ int   g_idx[NE * NB_MAX];
// conv weights as MMA B-fragments: [chunk][k16][col][q] = {bh0,bh1,bl0,bl1}
__device__ uint4 g_B1f[3 * 512];
__device__ uint4 g_B2f[8 * 1024];
__device__ uint4 g_B3f[9 * 1024];
// W1 as B-fragments: [e][196 k16][64 col][4 q]
__device__ uint4 g_W1f[NE * 196 * 256];

// ---------------- mma.sync helper ----------------
__device__ __forceinline__ void mma_bf16(float* c, uint32_t a0, uint32_t a1,
                                         uint32_t a2, uint32_t a3,
                                         uint32_t b0, uint32_t b1) {
    asm volatile(
        "mma.sync.aligned.m16n8k16.row.col.f32.bf16.bf16.f32 "
        "{%0,%1,%2,%3}, {%4,%5,%6,%7}, {%8,%9}, {%0,%1,%2,%3};"
        : "+f"(c[0]), "+f"(c[1]), "+f"(c[2]), "+f"(c[3])
        : "r"(a0), "r"(a1), "r"(a2), "r"(a3), "r"(b0), "r"(b1));
}

// ---------------- bf16 hi/lo packing ----------------
__device__ __forceinline__ void packpair(float a, float b, unsigned& h, unsigned& l) {
    __nv_bfloat162 hh = __floats2bfloat162_rn(a, b);
    float ra = a - __bfloat162float(__low2bfloat16(hh));
    float rb = b - __bfloat162float(__high2bfloat16(hh));
    __nv_bfloat162 ll = __floats2bfloat162_rn(ra, rb);
    h = *(unsigned*)&hh; l = *(unsigned*)&ll;
}

// ---------------- weight prepack + input split ----------------
__global__ void prep_kernel(const float* __restrict__ state,
                            const float* __restrict__ k1, const float* __restrict__ k2,
                            const float* __restrict__ k3, const float* __restrict__ W1,
                            int nB) {
    int t0 = blockIdx.x * blockDim.x + threadIdx.x;
    int stride = gridDim.x * blockDim.x;
    // conv1 input: one thread handles all 3 channels of a pixel pair (single sweep)
    int nx0 = nB * 3528;
    for (int i = t0; i < nx0; i += stride) {
        int b = i / 3528, rem = i % 3528;
        int h = rem / 42, wp = rem % 42;
        int base = ((b * 84 + h) * 84 + wp * 2) * 3;
        #pragma unroll
        for (int c = 0; c < 3; ++c) {
            unsigned hh, ll;
            packpair(state[base + c], state[base + 3 + c], hh, ll);
            g_x0[b * 10584 + c * 3528 + h * 42 + wp] = make_uint2(hh, ll);
        }
    }
    // conv1 B: kk = c*64 + kh*8 + kw
    for (int t = t0; t < 3 * 512; t += stride) {
        int ch = t / 512, rem = t % 512;
        int k16 = rem >> 7, col = (rem >> 2) & 31, q = rem & 3;
        int kb = ch * 64 + k16 * 16 + 2 * q;
        const float* w = k1 + col * 192;
        uint4 f;
        packpair(w[kb],     w[kb + 1], f.x, f.z);
        packpair(w[kb + 8], w[kb + 9], f.y, f.w);
        g_B1f[t] = f;
    }
    // conv2: kk = tap*32 + c -> k2[j*512 + c*16 + tap]
    for (int t = t0; t < 8 * 1024; t += stride) {
        int ch = t >> 10, rem = t & 1023;
        int k16 = rem >> 8, col = (rem >> 2) & 63, q = rem & 3;
        int kb = ch * 64 + k16 * 16 + 2 * q;
        const float* w = k2 + col * 512;
        auto W2f = [&](int kk) { int tap = kk >> 5, c = kk & 31; return w[c * 16 + tap]; };
        uint4 f;
        packpair(W2f(kb),     W2f(kb + 1), f.x, f.z);
        packpair(W2f(kb + 8), W2f(kb + 9), f.y, f.w);
        g_B2f[t] = f;
    }
    // conv3: kk = tap*64 + c -> k3[j*576 + c*9 + tap]
    for (int t = t0; t < 9 * 1024; t += stride) {
        int ch = t >> 10, rem = t & 1023;
        int k16 = rem >> 8, col = (rem >> 2) & 63, q = rem & 3;
        int kb = ch * 64 + k16 * 16 + 2 * q;
        const float* w = k3 + col * 576;
        auto W3f = [&](int kk) { int tap = kk >> 6, c = kk & 63; return w[c * 9 + tap]; };
        uint4 f;
        packpair(W3f(kb),     W3f(kb + 1), f.x, f.z);
        packpair(W3f(kb + 8), W3f(kb + 9), f.y, f.w);
        g_B3f[t] = f;
    }
    // W1 fragments, col-innermost iteration for coalesced W1 reads.
    // item t -> e, k16, q, col ; writes g_W1f[((e*196+k16)*64+col)*4+q]
    for (int t = t0; t < NE * 196 * 256; t += stride) {
        int col = t & 63, q = (t >> 6) & 3;
        int rest = t >> 8;
        int k16 = rest % 196, e = rest / 196;
        int kb = k16 * 16 + 2 * q;
        const float* We = W1 + (size_t)e * 200704;
        auto W1v = [&](int kk) { int p = kk >> 6, c = kk & 63; return We[(c * 49 + p) * 64 + col]; };
        uint4 f;
        packpair(W1v(kb),     W1v(kb + 1), f.x, f.z);
        packpair(W1v(kb + 8), W1v(kb + 9), f.y, f.w);
        g_W1f[((e * 196 + k16) * 64 + col) * 4 + q] = f;
    }
}

// ---------------- expert bucketing ----------------
__global__ void assign_kernel(const int* __restrict__ rm32, int n) {
    __shared__ int s_is64;
    int tid = threadIdx.x;
    if (tid == 0) s_is64 = 1;
    __syncthreads();
    for (int i = tid; i < 256; i += blockDim.x)
        if (rm32[2*i + 1] != 0) atomicExch(&s_is64, 0);
    if (tid < NE) g_cnt[tid] = 0;
    __syncthreads();
    int is64 = s_is64;
    const long long* rm64 = (const long long*)rm32;
    for (int b = tid; b < n; b += blockDim.x) {
        int e = is64 ? (int)rm64[b] : rm32[b];
        int pos = atomicAdd(&g_cnt[e], 1);
        g_idx[e * NB_MAX + pos] = b;
    }
}

// ---------------- conv-as-GEMM: direct-global interleaved fragments --------
// 128 threads (4 warps); warp handles TM m16-tiles (TM*16 rows).
// All A indices are in PAIR units (uint2 = {hi bf16x2, lo bf16x2}).
template<int CONV, int TM>
__global__ void __launch_bounds__(128, 4) conv_mma_kernel(
    const float* __restrict__ bias, int MTOT) {
    constexpr int KCH = (CONV == 1) ? 3 : ((CONV == 2) ? 8 : 9);
    constexpr int N   = (CONV == 1) ? 32 : 64;
    constexpr int POS = (CONV == 1) ? 400 : ((CONV == 2) ? 81 : 49);
    constexpr int OW  = (CONV == 1) ? 20 : ((CONV == 2) ? 9 : 7);
    constexpr int NT  = N / 8;
    constexpr int BCH = N * 16;

    const uint4* __restrict__ gB = (CONV == 1) ? g_B1f : ((CONV == 2) ? g_B2f : g_B3f);
    const uint2* __restrict__ X  = (CONV == 1) ? g_x0 : ((CONV == 2) ? g_x1 : g_x2);

    int tid = threadIdx.x, wid = tid >> 5, lane = tid & 31;
    int kp = lane & 3;            // pair offset within fragment
    int klo = kp * 2;
    int tb = blockIdx.x * (TM * 64);

    int orow[2 * TM];
    int pb[2 * TM];               // pair-unit row base
    #pragma unroll
    for (int i = 0; i < 2 * TM; ++i) {
        int gr = tb + wid * (TM * 16) + (i >> 1) * 16 + (i & 1) * 8 + (lane >> 2);
        orow[i] = gr;
        if (gr >= MTOT) gr = MTOT - 1;
        int b = gr / POS, p = gr % POS;
        int oh = p / OW, ow = p % OW;
        if (CONV == 1)      pb[i] = b * 10584 + oh * 168 + ow * 2;
        else if (CONV == 2) pb[i] = b * 6400  + oh * 640 + ow * 32;
        else                pb[i] = b * 2592  + oh * 288 + ow * 32;
    }

    float C[TM][NT][4];
    #pragma unroll
    for (int t = 0; t < TM; ++t)
        #pragma unroll
        for (int nt = 0; nt < NT; ++nt)
            #pragma unroll
            for (int q = 0; q < 4; ++q) C[t][nt][q] = 0.f;

    #pragma unroll 1
    for (int ch = 0; ch < KCH; ++ch) {
        int cb1 = 0;
        if (CONV == 1)      cb1 = ch * 3528;
        else if (CONV == 3) { int kh = ch / 3, kw = ch % 3; cb1 = kh * 288 + kw * 32; }

        #pragma unroll
        for (int k16 = 0; k16 < 4; ++k16) {
            int o0, o1;
            if (CONV == 1) {
                o0 = cb1 + k16 * 84 + kp;      // kh row k16*2
                o1 = o0 + 42;                  // next kh row (k+8)
            } else if (CONV == 2) {
                int tap = ch * 2 + (k16 >> 1);
                int kh = tap >> 2, kw = tap & 3;
                o0 = kh * 320 + kw * 16 + (k16 & 1) * 8 + kp;
                o1 = o0 + 4;
            } else {
                o0 = cb1 + k16 * 8 + kp;
                o1 = o0 + 4;
            }
            uint32_t ah[TM][4], al[TM][4];
            #pragma unroll
            for (int t = 0; t < TM; ++t) {
                const int r0 = pb[t*2], r1 = pb[t*2 + 1];
                uint2 u00 = X[r0 + o0];
                uint2 u10 = X[r1 + o0];
                uint2 u01 = X[r0 + o1];
                uint2 u11 = X[r1 + o1];
                ah[t][0] = u00.x; ah[t][1] = u10.x; ah[t][2] = u01.x; ah[t][3] = u11.x;
                al[t][0] = u00.y; al[t][1] = u10.y; al[t][2] = u01.y; al[t][3] = u11.y;
            }
            const uint4* bk = gB + ch * BCH + k16 * (N * 4) + (lane >> 2) * 4 + (lane & 3);
            #pragma unroll
            for (int nt = 0; nt < NT; ++nt) {
                uint4 f = bk[nt * 32];
                #pragma unroll
                for (int t = 0; t < TM; ++t) {
                    mma_bf16(C[t][nt], ah[t][0], ah[t][1], ah[t][2], ah[t][3], f.x, f.y);
                    mma_bf16(C[t][nt], ah[t][0], ah[t][1], ah[t][2], ah[t][3], f.z, f.w);
                    mma_bf16(C[t][nt], al[t][0], al[t][1], al[t][2], al[t][3], f.x, f.y);
                }
            }
        }
    }

    // ---- epilogue: bias + relu; fused {hi,lo} STG.64 ----
    #pragma unroll
    for (int t = 0; t < TM; ++t) {
        #pragma unroll
        for (int nt = 0; nt < NT; ++nt) {
            int col = nt * 8 + klo;
            float2 bv = *(const float2*)(bias + col);
            #pragma unroll
            for (int h = 0; h < 2; ++h) {
                int rw = orow[t*2 + h];
                if (rw >= MTOT) continue;
                float v0 = fmaxf(C[t][nt][h*2]     + bv.x, 0.f);
                float v1 = fmaxf(C[t][nt][h*2 + 1] + bv.y, 0.f);
                unsigned hh, ll;
                packpair(v0, v1, hh, ll);
                int cp = nt * 4 + kp;
                if (CONV == 1)      g_x1[(size_t)rw * 16 + cp] = make_uint2(hh, ll);
                else if (CONV == 2) g_x2[(size_t)rw * 32 + cp] = make_uint2(hh, ll);
                else                g_x3[(size_t)rw * 32 + cp] = make_uint2(hh, ll);
            }
        }
    }
}

// ---------------- MLP layer 1 on HMMA: [cnt_e,3136] x [3136,64] ------------
__global__ void __launch_bounds__(128, 4) mlp1_kernel(const float* __restrict__ B1) {
    int e = blockIdx.x;
    int cnt = g_cnt[e];
    int base = blockIdx.y * 128;
    if (base >= cnt) return;

    int tid = threadIdx.x, wid = tid >> 5, lane = tid & 31;
    int kp = lane & 3, klo = kp * 2;

    int sidr[4]; int orow[4];
    #pragma unroll
    for (int i = 0; i < 4; ++i) {
        int idx = base + wid * 32 + (i >> 1) * 16 + (i & 1) * 8 + (lane >> 2);
        orow[i] = idx;
        int cidx = (idx < cnt) ? idx : cnt - 1;
        sidr[i] = g_idx[e * NB_MAX + cidx] * 1568;   // pair units
    }

    float C[2][8][4];
    #pragma unroll
    for (int t = 0; t < 2; ++t)
        #pragma unroll
        for (int nt = 0; nt < 8; ++nt)
            #pragma unroll
            for (int q = 0; q < 4; ++q) C[t][nt][q] = 0.f;

    const uint4* gW = g_W1f + e * 196 * 256 + (lane >> 2) * 4 + (lane & 3);

    #pragma unroll 2
    for (int k16 = 0; k16 < 196; ++k16) {
        int o0 = k16 * 8 + kp, o1 = o0 + 4;
        uint32_t ah[2][4], al[2][4];
        #pragma unroll
        for (int t = 0; t < 2; ++t) {
            const int r0 = sidr[t*2], r1 = sidr[t*2 + 1];
            uint2 u00 = g_x3[r0 + o0];
            uint2 u10 = g_x3[r1 + o0];
            uint2 u01 = g_x3[r0 + o1];
            uint2 u11 = g_x3[r1 + o1];
            ah[t][0] = u00.x; ah[t][1] = u10.x; ah[t][2] = u01.x; ah[t][3] = u11.x;
            al[t][0] = u00.y; al[t][1] = u10.y; al[t][2] = u01.y; al[t][3] = u11.y;
        }
        const uint4* bk = gW + k16 * 256;
        #pragma unroll
        for (int nt = 0; nt < 8; ++nt) {
            uint4 f = bk[nt * 32];
            #pragma unroll
            for (int t = 0; t < 2; ++t) {
                mma_bf16(C[t][nt], ah[t][0], ah[t][1], ah[t][2], ah[t][3], f.x, f.y);
                mma_bf16(C[t][nt], ah[t][0], ah[t][1], ah[t][2], ah[t][3], f.z, f.w);
                mma_bf16(C[t][nt], al[t][0], al[t][1], al[t][2], al[t][3], f.x, f.y);
            }
        }
    }

    #pragma unroll
    for (int t = 0; t < 2; ++t) {
        #pragma unroll
        for (int nt = 0; nt < 8; ++nt) {
            int col = nt * 8 + klo;
            float2 bv = *(const float2*)(B1 + e * 64 + col);
            #pragma unroll
            for (int h = 0; h < 2; ++h) {
                int idx = orow[t*2 + h];
                if (idx >= cnt) continue;
                int sid = g_idx[e * NB_MAX + idx];
                float2 o;
                o.x = fmaxf(C[t][nt][h*2]     + bv.x, 0.f);
                o.y = fmaxf(C[t][nt][h*2 + 1] + bv.y, 0.f);
                *(float2*)(g_h1 + (size_t)sid * 64 + col) = o;
            }
        }
    }
}

// ---------------- MLP layers 2-6 ----------------
__global__ void __launch_bounds__(256) mlp2_kernel(
    const float* __restrict__ W2, const float* __restrict__ B2,
    const float* __restrict__ W3, const float* __restrict__ B3,
    const float* __restrict__ W4, const float* __restrict__ B4,
    const float* __restrict__ W5, const float* __restrict__ B5,
    const float* __restrict__ W6, const float* __restrict__ B6,
    float* __restrict__ out) {
    int e = blockIdx.x;
    int base = blockIdx.y * TB;
    int n = g_cnt[e] - base;
    if (n <= 0) return;
    if (n > TB) n = TB;

    __shared__ float hA[TB * 64], hB[TB * 64];
    __shared__ int   sid[TB];
    int tid = threadIdx.x, j = tid & 63, sq = tid >> 6;
    int s0 = sq * 8;

    if (tid < TB) sid[tid] = (tid < n) ? g_idx[e * NB_MAX + base + tid] : -1;
    __syncthreads();

    for (int i = tid; i < TB * 64; i += 256) {
        int s = i >> 6, d = i & 63;
        int bb = sid[s];
        hA[i] = (bb >= 0) ? g_h1[(size_t)bb * 64 + d] : 0.f;
    }
    __syncthreads();

    const float* Ws[4] = {W2, W3, W4, W5};
    const float* Bs[4] = {B2, B3, B4, B5};
    float* hin = hA;
    float* hout = hB;
    #pragma unroll 1
    for (int L = 0; L < 4; ++L) {
        const float* W = Ws[L] + (size_t)e * 4096;
        float bb = Bs[L][e * 64 + j];
        float a2[8];
        #pragma unroll
        for (int s = 0; s < 8; ++s) a2[s] = bb;
        for (int k = 0; k < 64; ++k) {
            float w = W[k * 64 + j];
            #pragma unroll
            for (int s = 0; s < 8; ++s)
                a2[s] = fmaf(hin[(s0 + s) * 64 + k], w, a2[s]);
        }
        #pragma unroll
        for (int s = 0; s < 8; ++s) hout[(s0 + s) * 64 + j] = fmaxf(a2[s], 0.f);
        __syncthreads();
        float* t = hin; hin = hout; hout = t;
    }

    if (j < NA) {
        const float* W6e = W6 + (size_t)e * 64 * NA;
        float b6 = B6[e * NA + j];
        int send = min(n, s0 + 8);
        for (int s = s0; s < send; ++s) {
            float a = b6;
            #pragma unroll
            for (int k = 0; k < 64; ++k)
                a = fmaf(hin[s * 64 + k], W6e[k * NA + j], a);
            out[(size_t)sid[s] * NA + j] = a;
        }
    }
}

// ---------------- launch ----------------
extern "C" void kernel_launch(void* const* d_in, const int* in_sizes, int n_in,
                              void* d_out, int out_size) {
    const float* state = (const float*)d_in[0];
    const int*   rm    = (const int*)d_in[1];
    const float* k1 = (const float*)d_in[2];
    const float* c1 = (const float*)d_in[3];
    const float* k2 = (const float*)d_in[4];
    const float* c2 = (const float*)d_in[5];
    const float* k3 = (const float*)d_in[6];
    const float* c3 = (const float*)d_in[7];
    const float* W1 = (const float*)d_in[8];
    const float* B1 = (const float*)d_in[9];
    const float* W2 = (const float*)d_in[10];
    const float* B2 = (const float*)d_in[11];
    const float* W3 = (const float*)d_in[12];
    const float* B3 = (const float*)d_in[13];
    const float* W4 = (const float*)d_in[14];
    const float* B4 = (const float*)d_in[15];
    const float* W5 = (const float*)d_in[16];
    const float* B5 = (const float*)d_in[17];
    const float* W6 = (const float*)d_in[18];
    const float* B6 = (const float*)d_in[19];
    float* out = (float*)d_out;

    int nB = in_sizes[1];
    if (nB > NB_MAX) nB = NB_MAX;

    int M1 = nB * 400, M2 = nB * 81, M3 = nB * 49;

    prep_kernel<<<1024, 256>>>(state, k1, k2, k3, W1, nB);
    assign_kernel<<<1, 256>>>(rm, nB);
    conv_mma_kernel<1, 4><<<(M1 + 255) / 256, 128>>>(c1, M1);
    conv_mma_kernel<2, 2><<<(M2 + 127) / 128, 128>>>(c2, M2);
    conv_mma_kernel<3, 2><<<(M3 + 127) / 128, 128>>>(c3, M3);
    mlp1_kernel<<<dim3(NE, (nB + 127) / 128), 128>>>(B1);
    mlp2_kernel<<<dim3(NE, (nB + TB - 1) / TB), 256>>>(
        W2, B2, W3, B3, W4, B4, W5, B5, W6, B6, out);
}

// round 14
// speedup vs baseline: 1.4032x; 1.4032x over previous
#include <cuda_runtime.h>
#include <cuda_bf16.h>
#include <cstdint>

// ---------------- problem constants ----------------
#define NB_MAX   2048
#define NE       8
#define NA       6
#define TB       32

// ---------------- scratch (device globals; no allocs allowed) ----------------
// All activations stored as uint2 {bf16x2_hi, bf16x2_lo} pairs.
__device__ uint2 g_x0[(size_t)NB_MAX * 3 * 84 * 42];   // [b][c][h][w/2]
__device__ uint2 g_x1[(size_t)NB_MAX * 400 * 16];      // [b*pos][c/2]
__device__ uint2 g_x2[(size_t)NB_MAX * 81 * 32];
__device__ uint2 g_x3[(size_t)NB_MAX * 49 * 32];
__device__ float g_h1[(size_t)NB_MAX * 64];
__device__ int   g_cnt[NE];
__device__ int   g_idx[NE * NB_MAX];
// conv weights as MMA B-fragments: [chunk][k16][col][q] = {bh0,bh1,bl0,bl1}
__device__ uint4 g_B1f[3 * 512];
__device__ uint4 g_B2f[8 * 1024];
__device__ uint4 g_B3f[9 * 1024];
// W1 as B-fragments: [e][196 k16][64 col][4 q]
__device__ uint4 g_W1f[NE * 196 * 256];

// ---------------- mma.sync helper ----------------
__device__ __forceinline__ void mma_bf16(float* c, uint32_t a0, uint32_t a1,
                                         uint32_t a2, uint32_t a3,
                                         uint32_t b0, uint32_t b1) {
    asm volatile(
        "mma.sync.aligned.m16n8k16.row.col.f32.bf16.bf16.f32 "
        "{%0,%1,%2,%3}, {%4,%5,%6,%7}, {%8,%9}, {%0,%1,%2,%3};"
        : "+f"(c[0]), "+f"(c[1]), "+f"(c[2]), "+f"(c[3])
        : "r"(a0), "r"(a1), "r"(a2), "r"(a3), "r"(b0), "r"(b1));
}

// ---------------- bf16 hi/lo packing ----------------
__device__ __forceinline__ void packpair(float a, float b, unsigned& h, unsigned& l) {
    __nv_bfloat162 hh = __floats2bfloat162_rn(a, b);
    float ra = a - __bfloat162float(__low2bfloat16(hh));
    float rb = b - __bfloat162float(__high2bfloat16(hh));
    __nv_bfloat162 ll = __floats2bfloat162_rn(ra, rb);
    h = *(unsigned*)&hh; l = *(unsigned*)&ll;
}

// ---------------- weight prepack + input split ----------------
__global__ void prep_kernel(const float* __restrict__ state,
                            const float* __restrict__ k1, const float* __restrict__ k2,
                            const float* __restrict__ k3, const float* __restrict__ W1,
                            int nB) {
    int t0 = blockIdx.x * blockDim.x + threadIdx.x;
    int stride = gridDim.x * blockDim.x;
    // conv1 input: one thread handles all 3 channels of a pixel pair (single sweep)
    int nx0 = nB * 3528;
    for (int i = t0; i < nx0; i += stride) {
        int b = i / 3528, rem = i % 3528;
        int h = rem / 42, wp = rem % 42;
        int base = ((b * 84 + h) * 84 + wp * 2) * 3;
        #pragma unroll
        for (int c = 0; c < 3; ++c) {
            unsigned hh, ll;
            packpair(state[base + c], state[base + 3 + c], hh, ll);
            g_x0[b * 10584 + c * 3528 + h * 42 + wp] = make_uint2(hh, ll);
        }
    }
    // conv1 B: kk = c*64 + kh*8 + kw
    for (int t = t0; t < 3 * 512; t += stride) {
        int ch = t / 512, rem = t % 512;
        int k16 = rem >> 7, col = (rem >> 2) & 31, q = rem & 3;
        int kb = ch * 64 + k16 * 16 + 2 * q;
        const float* w = k1 + col * 192;
        uint4 f;
        packpair(w[kb],     w[kb + 1], f.x, f.z);
        packpair(w[kb + 8], w[kb + 9], f.y, f.w);
        g_B1f[t] = f;
    }
    // conv2: kk = tap*32 + c -> k2[j*512 + c*16 + tap]
    for (int t = t0; t < 8 * 1024; t += stride) {
        int ch = t >> 10, rem = t & 1023;
        int k16 = rem >> 8, col = (rem >> 2) & 63, q = rem & 3;
        int kb = ch * 64 + k16 * 16 + 2 * q;
        const float* w = k2 + col * 512;
        auto W2f = [&](int kk) { int tap = kk >> 5, c = kk & 31; return w[c * 16 + tap]; };
        uint4 f;
        packpair(W2f(kb),     W2f(kb + 1), f.x, f.z);
        packpair(W2f(kb + 8), W2f(kb + 9), f.y, f.w);
        g_B2f[t] = f;
    }
    // conv3: kk = tap*64 + c -> k3[j*576 + c*9 + tap]
    for (int t = t0; t < 9 * 1024; t += stride) {
        int ch = t >> 10, rem = t & 1023;
        int k16 = rem >> 8, col = (rem >> 2) & 63, q = rem & 3;
        int kb = ch * 64 + k16 * 16 + 2 * q;
        const float* w = k3 + col * 576;
        auto W3f = [&](int kk) { int tap = kk >> 6, c = kk & 63; return w[c * 9 + tap]; };
        uint4 f;
        packpair(W3f(kb),     W3f(kb + 1), f.x, f.z);
        packpair(W3f(kb + 8), W3f(kb + 9), f.y, f.w);
        g_B3f[t] = f;
    }
    // W1 fragments, col-innermost iteration for coalesced W1 reads.
    for (int t = t0; t < NE * 196 * 256; t += stride) {
        int col = t & 63, q = (t >> 6) & 3;
        int rest = t >> 8;
        int k16 = rest % 196, e = rest / 196;
        int kb = k16 * 16 + 2 * q;
        const float* We = W1 + (size_t)e * 200704;
        auto W1v = [&](int kk) { int p = kk >> 6, c = kk & 63; return We[(c * 49 + p) * 64 + col]; };
        uint4 f;
        packpair(W1v(kb),     W1v(kb + 1), f.x, f.z);
        packpair(W1v(kb + 8), W1v(kb + 9), f.y, f.w);
        g_W1f[((e * 196 + k16) * 64 + col) * 4 + q] = f;
    }
}

// ---------------- expert bucketing ----------------
__global__ void assign_kernel(const int* __restrict__ rm32, int n) {
    __shared__ int s_is64;
    int tid = threadIdx.x;
    if (tid == 0) s_is64 = 1;
    __syncthreads();
    for (int i = tid; i < 256; i += blockDim.x)
        if (rm32[2*i + 1] != 0) atomicExch(&s_is64, 0);
    if (tid < NE) g_cnt[tid] = 0;
    __syncthreads();
    int is64 = s_is64;
    const long long* rm64 = (const long long*)rm32;
    for (int b = tid; b < n; b += blockDim.x) {
        int e = is64 ? (int)rm64[b] : rm32[b];
        int pos = atomicAdd(&g_cnt[e], 1);
        g_idx[e * NB_MAX + pos] = b;
    }
}

// ---------------- conv-as-GEMM: 256 threads = M-groups x N-halves ----------
// conv1 (N=32): 8 M-warps, no N split -> 256 rows/block.
// conv2/3 (N=64): 4 M-warps x 2 N-halves -> 128 rows/block.
// Per warp: TM=2 m16 tiles x NT=4 n8 tiles. C = 32 regs.
template<int CONV>
__global__ void __launch_bounds__(256) conv_mma_kernel(
    const float* __restrict__ bias, int MTOT) {
    constexpr int KCH = (CONV == 1) ? 3 : ((CONV == 2) ? 8 : 9);
    constexpr int N   = (CONV == 1) ? 32 : 64;
    constexpr int POS = (CONV == 1) ? 400 : ((CONV == 2) ? 81 : 49);
    constexpr int OW  = (CONV == 1) ? 20 : ((CONV == 2) ? 9 : 7);
    constexpr int NT  = 4;
    constexpr int MW  = (CONV == 1) ? 8 : 4;     // M-warps per block
    constexpr int BCH = N * 16;                  // uint4 per B chunk

    const uint4* __restrict__ gB = (CONV == 1) ? g_B1f : ((CONV == 2) ? g_B2f : g_B3f);
    const uint2* __restrict__ X  = (CONV == 1) ? g_x0 : ((CONV == 2) ? g_x1 : g_x2);

    int tid = threadIdx.x, wid = tid >> 5, lane = tid & 31;
    int mw = (CONV == 1) ? wid : (wid >> 1);
    int nh = (CONV == 1) ? 0   : (wid & 1);
    int kp = lane & 3, klo = kp * 2;
    int tb = blockIdx.x * (MW * 32);

    int orow[4];
    int pb[4];               // pair-unit row base
    #pragma unroll
    for (int i = 0; i < 4; ++i) {
        int gr = tb + mw * 32 + (i >> 1) * 16 + (i & 1) * 8 + (lane >> 2);
        orow[i] = gr;
        if (gr >= MTOT) gr = MTOT - 1;
        int b = gr / POS, p = gr % POS;
        int oh = p / OW, ow = p % OW;
        if (CONV == 1)      pb[i] = b * 10584 + oh * 168 + ow * 2;
        else if (CONV == 2) pb[i] = b * 6400  + oh * 640 + ow * 32;
        else                pb[i] = b * 2592  + oh * 288 + ow * 32;
    }

    float C[2][NT][4];
    #pragma unroll
    for (int t = 0; t < 2; ++t)
        #pragma unroll
        for (int nt = 0; nt < NT; ++nt)
            #pragma unroll
            for (int q = 0; q < 4; ++q) C[t][nt][q] = 0.f;

    #pragma unroll 1
    for (int ch = 0; ch < KCH; ++ch) {
        int cb1 = 0;
        if (CONV == 1)      cb1 = ch * 3528;
        else if (CONV == 3) { int kh = ch / 3, kw = ch % 3; cb1 = kh * 288 + kw * 32; }

        #pragma unroll
        for (int k16 = 0; k16 < 4; ++k16) {
            int o0, o1;
            if (CONV == 1) {
                o0 = cb1 + k16 * 84 + kp;
                o1 = o0 + 42;
            } else if (CONV == 2) {
                int tap = ch * 2 + (k16 >> 1);
                int kh = tap >> 2, kw = tap & 3;
                o0 = kh * 320 + kw * 16 + (k16 & 1) * 8 + kp;
                o1 = o0 + 4;
            } else {
                o0 = cb1 + k16 * 8 + kp;
                o1 = o0 + 4;
            }
            uint32_t ah[2][4], al[2][4];
            #pragma unroll
            for (int t = 0; t < 2; ++t) {
                const int r0 = pb[t*2], r1 = pb[t*2 + 1];
                uint2 u00 = X[r0 + o0];
                uint2 u10 = X[r1 + o0];
                uint2 u01 = X[r0 + o1];
                uint2 u11 = X[r1 + o1];
                ah[t][0] = u00.x; ah[t][1] = u10.x; ah[t][2] = u01.x; ah[t][3] = u11.x;
                al[t][0] = u00.y; al[t][1] = u10.y; al[t][2] = u01.y; al[t][3] = u11.y;
            }
            const uint4* bk = gB + ch * BCH + k16 * (N * 4) + nh * 128
                              + (lane >> 2) * 4 + (lane & 3);
            #pragma unroll
            for (int nt = 0; nt < NT; ++nt) {
                uint4 f = bk[nt * 32];
                #pragma unroll
                for (int t = 0; t < 2; ++t) {
                    mma_bf16(C[t][nt], ah[t][0], ah[t][1], ah[t][2], ah[t][3], f.x, f.y);
                    mma_bf16(C[t][nt], ah[t][0], ah[t][1], ah[t][2], ah[t][3], f.z, f.w);
                    mma_bf16(C[t][nt], al[t][0], al[t][1], al[t][2], al[t][3], f.x, f.y);
                }
            }
        }
    }

    // ---- epilogue: bias + relu; fused {hi,lo} STG.64 ----
    #pragma unroll
    for (int t = 0; t < 2; ++t) {
        #pragma unroll
        for (int nt = 0; nt < NT; ++nt) {
            int col = nh * 32 + nt * 8 + klo;
            float2 bv = *(const float2*)(bias + col);
            #pragma unroll
            for (int h = 0; h < 2; ++h) {
                int rw = orow[t*2 + h];
                if (rw >= MTOT) continue;
                float v0 = fmaxf(C[t][nt][h*2]     + bv.x, 0.f);
                float v1 = fmaxf(C[t][nt][h*2 + 1] + bv.y, 0.f);
                unsigned hh, ll;
                packpair(v0, v1, hh, ll);
                int cp = nh * 16 + nt * 4 + kp;
                if (CONV == 1)      g_x1[(size_t)rw * 16 + cp] = make_uint2(hh, ll);
                else if (CONV == 2) g_x2[(size_t)rw * 32 + cp] = make_uint2(hh, ll);
                else                g_x3[(size_t)rw * 32 + cp] = make_uint2(hh, ll);
            }
        }
    }
}

// ---------------- MLP layer 1 on HMMA: 4 M-warps x 2 N-halves --------------
__global__ void __launch_bounds__(256) mlp1_kernel(const float* __restrict__ B1) {
    int e = blockIdx.x;
    int cnt = g_cnt[e];
    int base = blockIdx.y * 128;
    if (base >= cnt) return;

    int tid = threadIdx.x, wid = tid >> 5, lane = tid & 31;
    int mw = wid >> 1, nh = wid & 1;
    int kp = lane & 3, klo = kp * 2;

    int sidr[4]; int orow[4];
    #pragma unroll
    for (int i = 0; i < 4; ++i) {
        int idx = base + mw * 32 + (i >> 1) * 16 + (i & 1) * 8 + (lane >> 2);
        orow[i] = idx;
        int cidx = (idx < cnt) ? idx : cnt - 1;
        sidr[i] = g_idx[e * NB_MAX + cidx] * 1568;   // pair units
    }

    float C[2][4][4];
    #pragma unroll
    for (int t = 0; t < 2; ++t)
        #pragma unroll
        for (int nt = 0; nt < 4; ++nt)
            #pragma unroll
            for (int q = 0; q < 4; ++q) C[t][nt][q] = 0.f;

    const uint4* gW = g_W1f + e * 196 * 256 + nh * 128 + (lane >> 2) * 4 + (lane & 3);

    #pragma unroll 2
    for (int k16 = 0; k16 < 196; ++k16) {
        int o0 = k16 * 8 + kp, o1 = o0 + 4;
        uint32_t ah[2][4], al[2][4];
        #pragma unroll
        for (int t = 0; t < 2; ++t) {
            const int r0 = sidr[t*2], r1 = sidr[t*2 + 1];
            uint2 u00 = g_x3[r0 + o0];
            uint2 u10 = g_x3[r1 + o0];
            uint2 u01 = g_x3[r0 + o1];
            uint2 u11 = g_x3[r1 + o1];
            ah[t][0] = u00.x; ah[t][1] = u10.x; ah[t][2] = u01.x; ah[t][3] = u11.x;
            al[t][0] = u00.y; al[t][1] = u10.y; al[t][2] = u01.y; al[t][3] = u11.y;
        }
        const uint4* bk = gW + k16 * 256;
        #pragma unroll
        for (int nt = 0; nt < 4; ++nt) {
            uint4 f = bk[nt * 32];
            #pragma unroll
            for (int t = 0; t < 2; ++t) {
                mma_bf16(C[t][nt], ah[t][0], ah[t][1], ah[t][2], ah[t][3], f.x, f.y);
                mma_bf16(C[t][nt], ah[t][0], ah[t][1], ah[t][2], ah[t][3], f.z, f.w);
                mma_bf16(C[t][nt], al[t][0], al[t][1], al[t][2], al[t][3], f.x, f.y);
            }
        }
    }

    #pragma unroll
    for (int t = 0; t < 2; ++t) {
        #pragma unroll
        for (int nt = 0; nt < 4; ++nt) {
            int col = nh * 32 + nt * 8 + klo;
            float2 bv = *(const float2*)(B1 + e * 64 + col);
            #pragma unroll
            for (int h = 0; h < 2; ++h) {
                int idx = orow[t*2 + h];
                if (idx >= cnt) continue;
                int sid = g_idx[e * NB_MAX + idx];
                float2 o;
                o.x = fmaxf(C[t][nt][h*2]     + bv.x, 0.f);
                o.y = fmaxf(C[t][nt][h*2 + 1] + bv.y, 0.f);
                *(float2*)(g_h1 + (size_t)sid * 64 + col) = o;
            }
        }
    }
}

// ---------------- MLP layers 2-6 ----------------
__global__ void __launch_bounds__(256) mlp2_kernel(
    const float* __restrict__ W2, const float* __restrict__ B2,
    const float* __restrict__ W3, const float* __restrict__ B3,
    const float* __restrict__ W4, const float* __restrict__ B4,
    const float* __restrict__ W5, const float* __restrict__ B5,
    const float* __restrict__ W6, const float* __restrict__ B6,
    float* __restrict__ out) {
    int e = blockIdx.x;
    int base = blockIdx.y * TB;
    int n = g_cnt[e] - base;
    if (n <= 0) return;
    if (n > TB) n = TB;

    __shared__ float hA[TB * 64], hB[TB * 64];
    __shared__ int   sid[TB];
    int tid = threadIdx.x, j = tid & 63, sq = tid >> 6;
    int s0 = sq * 8;

    if (tid < TB) sid[tid] = (tid < n) ? g_idx[e * NB_MAX + base + tid] : -1;
    __syncthreads();

    for (int i = tid; i < TB * 64; i += 256) {
        int s = i >> 6, d = i & 63;
        int bb = sid[s];
        hA[i] = (bb >= 0) ? g_h1[(size_t)bb * 64 + d] : 0.f;
    }
    __syncthreads();

    const float* Ws[4] = {W2, W3, W4, W5};
    const float* Bs[4] = {B2, B3, B4, B5};
    float* hin = hA;
    float* hout = hB;
    #pragma unroll 1
    for (int L = 0; L < 4; ++L) {
        const float* W = Ws[L] + (size_t)e * 4096;
        float bb = Bs[L][e * 64 + j];
        float a2[8];
        #pragma unroll
        for (int s = 0; s < 8; ++s) a2[s] = bb;
        for (int k = 0; k < 64; ++k) {
            float w = W[k * 64 + j];
            #pragma unroll
            for (int s = 0; s < 8; ++s)
                a2[s] = fmaf(hin[(s0 + s) * 64 + k], w, a2[s]);
        }
        #pragma unroll
        for (int s = 0; s < 8; ++s) hout[(s0 + s) * 64 + j] = fmaxf(a2[s], 0.f);
        __syncthreads();
        float* t = hin; hin = hout; hout = t;
    }

    if (j < NA) {
        const float* W6e = W6 + (size_t)e * 64 * NA;
        float b6 = B6[e * NA + j];
        int send = min(n, s0 + 8);
        for (int s = s0; s < send; ++s) {
            float a = b6;
            #pragma unroll
            for (int k = 0; k < 64; ++k)
                a = fmaf(hin[s * 64 + k], W6e[k * NA + j], a);
            out[(size_t)sid[s] * NA + j] = a;
        }
    }
}

// ---------------- launch ----------------
extern "C" void kernel_launch(void* const* d_in, const int* in_sizes, int n_in,
                              void* d_out, int out_size) {
    const float* state = (const float*)d_in[0];
    const int*   rm    = (const int*)d_in[1];
    const float* k1 = (const float*)d_in[2];
    const float* c1 = (const float*)d_in[3];
    const float* k2 = (const float*)d_in[4];
    const float* c2 = (const float*)d_in[5];
    const float* k3 = (const float*)d_in[6];
    const float* c3 = (const float*)d_in[7];
    const float* W1 = (const float*)d_in[8];
    const float* B1 = (const float*)d_in[9];
    const float* W2 = (const float*)d_in[10];
    const float* B2 = (const float*)d_in[11];
    const float* W3 = (const float*)d_in[12];
    const float* B3 = (const float*)d_in[13];
    const float* W4 = (const float*)d_in[14];
    const float* B4 = (const float*)d_in[15];
    const float* W5 = (const float*)d_in[16];
    const float* B5 = (const float*)d_in[17];
    const float* W6 = (const float*)d_in[18];
    const float* B6 = (const float*)d_in[19];
    float* out = (float*)d_out;

    int nB = in_sizes[1];
    if (nB > NB_MAX) nB = NB_MAX;

    int M1 = nB * 400, M2 = nB * 81, M3 = nB * 49;

    prep_kernel<<<1024, 256>>>(state, k1, k2, k3, W1, nB);
    assign_kernel<<<1, 256>>>(rm, nB);
    conv_mma_kernel<1><<<(M1 + 255) / 256, 256>>>(c1, M1);
    conv_mma_kernel<2><<<(M2 + 127) / 128, 256>>>(c2, M2);
    conv_mma_kernel<3><<<(M3 + 127) / 128, 256>>>(c3, M3);
    mlp1_kernel<<<dim3(NE, (nB + 127) / 128), 256>>>(B1);
    mlp2_kernel<<<dim3(NE, (nB + TB - 1) / TB), 256>>>(
        W2, B2, W3, B3, W4, B4, W5, B5, W6, B6, out);
}

// round 15
// speedup vs baseline: 1.4140x; 1.0077x over previous
#include <cuda_runtime.h>
#include <cuda_bf16.h>
#include <cstdint>

// ---------------- problem constants ----------------
#define NB_MAX   2048
#define NE       8
#define NA       6
#define TB       32

// ---------------- scratch (device globals; no allocs allowed) ----------------
// All activations stored as uint2 {bf16x2_hi, bf16x2_lo} pairs.
__device__ uint2 g_x0[(size_t)NB_MAX * 3 * 84 * 42];   // [b][c][h][w/2]
// x1/x2/x3 declared as uint4 for guaranteed 16B alignment (accessed as uint2/uint4)
__device__ uint4 g_x1r[(size_t)NB_MAX * 400 * 8];
__device__ uint4 g_x2r[(size_t)NB_MAX * 81 * 16];
__device__ uint4 g_x3r[(size_t)NB_MAX * 49 * 16];
#define g_x1 ((uint2*)g_x1r)
#define g_x2 ((uint2*)g_x2r)
#define g_x3 ((uint2*)g_x3r)
__device__ float g_h1[(size_t)NB_MAX * 64];
__device__ int   g_cnt[NE];
__device__ int   g_idx[NE * NB_MAX];
// conv weights as MMA B-fragments: [chunk][k16][col][q] = {bh0,bh1,bl0,bl1}
// B1f: plain k-order. B2f/B3f/W1f: PERMUTED k-order (word q = logical elems base+4q..+3)
__device__ uint4 g_B1f[3 * 512];
__device__ uint4 g_B2f[8 * 1024];
__device__ uint4 g_B3f[9 * 1024];
__device__ uint4 g_W1f[NE * 196 * 256];

// ---------------- mma.sync helper ----------------
__device__ __forceinline__ void mma_bf16(float* c, uint32_t a0, uint32_t a1,
                                         uint32_t a2, uint32_t a3,
                                         uint32_t b0, uint32_t b1) {
    asm volatile(
        "mma.sync.aligned.m16n8k16.row.col.f32.bf16.bf16.f32 "
        "{%0,%1,%2,%3}, {%4,%5,%6,%7}, {%8,%9}, {%0,%1,%2,%3};"
        : "+f"(c[0]), "+f"(c[1]), "+f"(c[2]), "+f"(c[3])
        : "r"(a0), "r"(a1), "r"(a2), "r"(a3), "r"(b0), "r"(b1));
}

// ---------------- bf16 hi/lo packing ----------------
__device__ __forceinline__ void packpair(float a, float b, unsigned& h, unsigned& l) {
    __nv_bfloat162 hh = __floats2bfloat162_rn(a, b);
    float ra = a - __bfloat162float(__low2bfloat16(hh));
    float rb = b - __bfloat162float(__high2bfloat16(hh));
    __nv_bfloat162 ll = __floats2bfloat162_rn(ra, rb);
    h = *(unsigned*)&hh; l = *(unsigned*)&ll;
}

// ---------------- weight prepack + input split ----------------
__global__ void prep_kernel(const float* __restrict__ state,
                            const float* __restrict__ k1, const float* __restrict__ k2,
                            const float* __restrict__ k3, const float* __restrict__ W1,
                            int nB) {
    int t0 = blockIdx.x * blockDim.x + threadIdx.x;
    int stride = gridDim.x * blockDim.x;
    // conv1 input: one thread handles all 3 channels of a pixel pair (single sweep)
    int nx0 = nB * 3528;
    for (int i = t0; i < nx0; i += stride) {
        int b = i / 3528, rem = i % 3528;
        int h = rem / 42, wp = rem % 42;
        int base = ((b * 84 + h) * 84 + wp * 2) * 3;
        #pragma unroll
        for (int c = 0; c < 3; ++c) {
            unsigned hh, ll;
            packpair(state[base + c], state[base + 3 + c], hh, ll);
            g_x0[b * 10584 + c * 3528 + h * 42 + wp] = make_uint2(hh, ll);
        }
    }
    // conv1 B (plain order): kk = c*64 + kh*8 + kw
    for (int t = t0; t < 3 * 512; t += stride) {
        int ch = t / 512, rem = t % 512;
        int k16 = rem >> 7, col = (rem >> 2) & 31, q = rem & 3;
        int kb = ch * 64 + k16 * 16 + 2 * q;
        const float* w = k1 + col * 192;
        uint4 f;
        packpair(w[kb],     w[kb + 1], f.x, f.z);
        packpair(w[kb + 8], w[kb + 9], f.y, f.w);
        g_B1f[t] = f;
    }
    // conv2 B (PERMUTED): word q covers logical elems base+4q..+3; kk = tap*32 + c
    for (int t = t0; t < 8 * 1024; t += stride) {
        int ch = t >> 10, rem = t & 1023;
        int k16 = rem >> 8, col = (rem >> 2) & 63, q = rem & 3;
        int kb = ch * 64 + k16 * 16 + 4 * q;
        const float* w = k2 + col * 512;
        auto W2f = [&](int kk) { int tap = kk >> 5, c = kk & 31; return w[c * 16 + tap]; };
        uint4 f;
        packpair(W2f(kb),     W2f(kb + 1), f.x, f.z);
        packpair(W2f(kb + 2), W2f(kb + 3), f.y, f.w);
        g_B2f[t] = f;
    }
    // conv3 B (PERMUTED): kk = tap*64 + c
    for (int t = t0; t < 9 * 1024; t += stride) {
        int ch = t >> 10, rem = t & 1023;
        int k16 = rem >> 8, col = (rem >> 2) & 63, q = rem & 3;
        int kb = ch * 64 + k16 * 16 + 4 * q;
        const float* w = k3 + col * 576;
        auto W3f = [&](int kk) { int tap = kk >> 6, c = kk & 63; return w[c * 9 + tap]; };
        uint4 f;
        packpair(W3f(kb),     W3f(kb + 1), f.x, f.z);
        packpair(W3f(kb + 2), W3f(kb + 3), f.y, f.w);
        g_B3f[t] = f;
    }
    // W1 fragments (PERMUTED), col-innermost for coalesced W1 reads.
    for (int t = t0; t < NE * 196 * 256; t += stride) {
        int col = t & 63, q = (t >> 6) & 3;
        int rest = t >> 8;
        int k16 = rest % 196, e = rest / 196;
        int kb = k16 * 16 + 4 * q;
        const float* We = W1 + (size_t)e * 200704;
        auto W1v = [&](int kk) { int p = kk >> 6, c = kk & 63; return We[(c * 49 + p) * 64 + col]; };
        uint4 f;
        packpair(W1v(kb),     W1v(kb + 1), f.x, f.z);
        packpair(W1v(kb + 2), W1v(kb + 3), f.y, f.w);
        g_W1f[((e * 196 + k16) * 64 + col) * 4 + q] = f;
    }
}

// ---------------- expert bucketing ----------------
__global__ void assign_kernel(const int* __restrict__ rm32, int n) {
    __shared__ int s_is64;
    int tid = threadIdx.x;
    if (tid == 0) s_is64 = 1;
    __syncthreads();
    for (int i = tid; i < 256; i += blockDim.x)
        if (rm32[2*i + 1] != 0) atomicExch(&s_is64, 0);
    if (tid < NE) g_cnt[tid] = 0;
    __syncthreads();
    int is64 = s_is64;
    const long long* rm64 = (const long long*)rm32;
    for (int b = tid; b < n; b += blockDim.x) {
        int e = is64 ? (int)rm64[b] : rm32[b];
        int pos = atomicAdd(&g_cnt[e], 1);
        g_idx[e * NB_MAX + pos] = b;
    }
}

// ---------------- conv-as-GEMM: 256 threads = M-groups x N-halves ----------
// conv1 (N=32): 8 M-warps, plain k-order, 2x uint2 loads.
// conv2/3 (N=64): 4 M-warps x 2 N-halves, PERMUTED k-order, 1x uint4 load.
template<int CONV>
__global__ void __launch_bounds__(256) conv_mma_kernel(
    const float* __restrict__ bias, int MTOT) {
    constexpr int KCH = (CONV == 1) ? 3 : ((CONV == 2) ? 8 : 9);
    constexpr int N   = (CONV == 1) ? 32 : 64;
    constexpr int POS = (CONV == 1) ? 400 : ((CONV == 2) ? 81 : 49);
    constexpr int OW  = (CONV == 1) ? 20 : ((CONV == 2) ? 9 : 7);
    constexpr int NT  = 4;
    constexpr int MW  = (CONV == 1) ? 8 : 4;
    constexpr int BCH = N * 16;

    const uint4* __restrict__ gB = (CONV == 1) ? g_B1f : ((CONV == 2) ? g_B2f : g_B3f);
    const uint2* __restrict__ X  = (CONV == 1) ? g_x0 : ((CONV == 2) ? g_x1 : g_x2);

    int tid = threadIdx.x, wid = tid >> 5, lane = tid & 31;
    int mw = (CONV == 1) ? wid : (wid >> 1);
    int nh = (CONV == 1) ? 0   : (wid & 1);
    int kp = lane & 3, klo = kp * 2;
    int tb = blockIdx.x * (MW * 32);

    int orow[4];
    int pb[4];               // pair-unit row base
    #pragma unroll
    for (int i = 0; i < 4; ++i) {
        int gr = tb + mw * 32 + (i >> 1) * 16 + (i & 1) * 8 + (lane >> 2);
        orow[i] = gr;
        if (gr >= MTOT) gr = MTOT - 1;
        int b = gr / POS, p = gr % POS;
        int oh = p / OW, ow = p % OW;
        if (CONV == 1)      pb[i] = b * 10584 + oh * 168 + ow * 2;
        else if (CONV == 2) pb[i] = b * 6400  + oh * 640 + ow * 32;
        else                pb[i] = b * 2592  + oh * 288 + ow * 32;
    }

    float C[2][NT][4];
    #pragma unroll
    for (int t = 0; t < 2; ++t)
        #pragma unroll
        for (int nt = 0; nt < NT; ++nt)
            #pragma unroll
            for (int q = 0; q < 4; ++q) C[t][nt][q] = 0.f;

    #pragma unroll 1
    for (int ch = 0; ch < KCH; ++ch) {
        int cb1 = 0;
        if (CONV == 1)      cb1 = ch * 3528;
        else if (CONV == 3) { int kh = ch / 3, kw = ch % 3; cb1 = kh * 288 + kw * 32; }

        #pragma unroll
        for (int k16 = 0; k16 < 4; ++k16) {
            uint32_t ah[2][4], al[2][4];
            if (CONV == 1) {
                int o0 = cb1 + k16 * 84 + kp;
                int o1 = o0 + 42;
                #pragma unroll
                for (int t = 0; t < 2; ++t) {
                    const int r0 = pb[t*2], r1 = pb[t*2 + 1];
                    uint2 u00 = X[r0 + o0];
                    uint2 u10 = X[r1 + o0];
                    uint2 u01 = X[r0 + o1];
                    uint2 u11 = X[r1 + o1];
                    ah[t][0] = u00.x; ah[t][1] = u10.x; ah[t][2] = u01.x; ah[t][3] = u11.x;
                    al[t][0] = u00.y; al[t][1] = u10.y; al[t][2] = u01.y; al[t][3] = u11.y;
                }
            } else {
                int o;
                if (CONV == 2) {
                    int tap = ch * 2 + (k16 >> 1);
                    int kh = tap >> 2, kw = tap & 3;
                    o = kh * 320 + kw * 16 + (k16 & 1) * 8 + kp * 2;
                } else {
                    o = cb1 + k16 * 8 + kp * 2;
                }
                #pragma unroll
                for (int t = 0; t < 2; ++t) {
                    uint4 v0 = *(const uint4*)(X + pb[t*2]     + o);
                    uint4 v1 = *(const uint4*)(X + pb[t*2 + 1] + o);
                    ah[t][0] = v0.x; ah[t][1] = v1.x; ah[t][2] = v0.z; ah[t][3] = v1.z;
                    al[t][0] = v0.y; al[t][1] = v1.y; al[t][2] = v0.w; al[t][3] = v1.w;
                }
            }
            const uint4* bk = gB + ch * BCH + k16 * (N * 4) + nh * 128
                              + (lane >> 2) * 4 + (lane & 3);
            #pragma unroll
            for (int nt = 0; nt < NT; ++nt) {
                uint4 f = bk[nt * 32];
                #pragma unroll
                for (int t = 0; t < 2; ++t) {
                    mma_bf16(C[t][nt], ah[t][0], ah[t][1], ah[t][2], ah[t][3], f.x, f.y);
                    mma_bf16(C[t][nt], ah[t][0], ah[t][1], ah[t][2], ah[t][3], f.z, f.w);
                    mma_bf16(C[t][nt], al[t][0], al[t][1], al[t][2], al[t][3], f.x, f.y);
                }
            }
        }
    }

    // ---- epilogue: bias + relu; fused {hi,lo} STG.64 ----
    #pragma unroll
    for (int t = 0; t < 2; ++t) {
        #pragma unroll
        for (int nt = 0; nt < NT; ++nt) {
            int col = nh * 32 + nt * 8 + klo;
            float2 bv = *(const float2*)(bias + col);
            #pragma unroll
            for (int h = 0; h < 2; ++h) {
                int rw = orow[t*2 + h];
                if (rw >= MTOT) continue;
                float v0 = fmaxf(C[t][nt][h*2]     + bv.x, 0.f);
                float v1 = fmaxf(C[t][nt][h*2 + 1] + bv.y, 0.f);
                unsigned hh, ll;
                packpair(v0, v1, hh, ll);
                int cp = nh * 16 + nt * 4 + kp;
                if (CONV == 1)      g_x1[(size_t)rw * 16 + cp] = make_uint2(hh, ll);
                else if (CONV == 2) g_x2[(size_t)rw * 32 + cp] = make_uint2(hh, ll);
                else                g_x3[(size_t)rw * 32 + cp] = make_uint2(hh, ll);
            }
        }
    }
}

// ---------------- MLP layer 1 on HMMA: 4 M-warps x 2 N-halves (PERMUTED) ---
__global__ void __launch_bounds__(256) mlp1_kernel(const float* __restrict__ B1) {
    int e = blockIdx.x;
    int cnt = g_cnt[e];
    int base = blockIdx.y * 128;
    if (base >= cnt) return;

    int tid = threadIdx.x, wid = tid >> 5, lane = tid & 31;
    int mw = wid >> 1, nh = wid & 1;
    int kp = lane & 3, klo = kp * 2;

    int sidr[4]; int orow[4];
    #pragma unroll
    for (int i = 0; i < 4; ++i) {
        int idx = base + mw * 32 + (i >> 1) * 16 + (i & 1) * 8 + (lane >> 2);
        orow[i] = idx;
        int cidx = (idx < cnt) ? idx : cnt - 1;
        sidr[i] = g_idx[e * NB_MAX + cidx] * 1568;   // pair units
    }

    float C[2][4][4];
    #pragma unroll
    for (int t = 0; t < 2; ++t)
        #pragma unroll
        for (int nt = 0; nt < 4; ++nt)
            #pragma unroll
            for (int q = 0; q < 4; ++q) C[t][nt][q] = 0.f;

    const uint4* gW = g_W1f + e * 196 * 256 + nh * 128 + (lane >> 2) * 4 + (lane & 3);

    #pragma unroll 2
    for (int k16 = 0; k16 < 196; ++k16) {
        int o = k16 * 8 + kp * 2;
        uint32_t ah[2][4], al[2][4];
        #pragma unroll
        for (int t = 0; t < 2; ++t) {
            uint4 v0 = *(const uint4*)(g_x3 + sidr[t*2]     + o);
            uint4 v1 = *(const uint4*)(g_x3 + sidr[t*2 + 1] + o);
            ah[t][0] = v0.x; ah[t][1] = v1.x; ah[t][2] = v0.z; ah[t][3] = v1.z;
            al[t][0] = v0.y; al[t][1] = v1.y; al[t][2] = v0.w; al[t][3] = v1.w;
        }
        const uint4* bk = gW + k16 * 256;
        #pragma unroll
        for (int nt = 0; nt < 4; ++nt) {
            uint4 f = bk[nt * 32];
            #pragma unroll
            for (int t = 0; t < 2; ++t) {
                mma_bf16(C[t][nt], ah[t][0], ah[t][1], ah[t][2], ah[t][3], f.x, f.y);
                mma_bf16(C[t][nt], ah[t][0], ah[t][1], ah[t][2], ah[t][3], f.z, f.w);
                mma_bf16(C[t][nt], al[t][0], al[t][1], al[t][2], al[t][3], f.x, f.y);
            }
        }
    }

    #pragma unroll
    for (int t = 0; t < 2; ++t) {
        #pragma unroll
        for (int nt = 0; nt < 4; ++nt) {
            int col = nh * 32 + nt * 8 + klo;
            float2 bv = *(const float2*)(B1 + e * 64 + col);
            #pragma unroll
            for (int h = 0; h < 2; ++h) {
                int idx = orow[t*2 + h];
                if (idx >= cnt) continue;
                int sid = g_idx[e * NB_MAX + idx];
                float2 o2;
                o2.x = fmaxf(C[t][nt][h*2]     + bv.x, 0.f);
                o2.y = fmaxf(C[t][nt][h*2 + 1] + bv.y, 0.f);
                *(float2*)(g_h1 + (size_t)sid * 64 + col) = o2;
            }
        }
    }
}

// ---------------- MLP layers 2-6 ----------------
__global__ void __launch_bounds__(256) mlp2_kernel(
    const float* __restrict__ W2, const float* __restrict__ B2,
    const float* __restrict__ W3, const float* __restrict__ B3,
    const float* __restrict__ W4, const float* __restrict__ B4,
    const float* __restrict__ W5, const float* __restrict__ B5,
    const float* __restrict__ W6, const float* __restrict__ B6,
    float* __restrict__ out) {
    int e = blockIdx.x;
    int base = blockIdx.y * TB;
    int n = g_cnt[e] - base;
    if (n <= 0) return;
    if (n > TB) n = TB;

    __shared__ float hA[TB * 64], hB[TB * 64];
    __shared__ int   sid[TB];
    int tid = threadIdx.x, j = tid & 63, sq = tid >> 6;
    int s0 = sq * 8;

    if (tid < TB) sid[tid] = (tid < n) ? g_idx[e * NB_MAX + base + tid] : -1;
    __syncthreads();

    for (int i = tid; i < TB * 64; i += 256) {
        int s = i >> 6, d = i & 63;
        int bb = sid[s];
        hA[i] = (bb >= 0) ? g_h1[(size_t)bb * 64 + d] : 0.f;
    }
    __syncthreads();

    const float* Ws[4] = {W2, W3, W4, W5};
    const float* Bs[4] = {B2, B3, B4, B5};
    float* hin = hA;
    float* hout = hB;
    #pragma unroll 1
    for (int L = 0; L < 4; ++L) {
        const float* W = Ws[L] + (size_t)e * 4096;
        float bb = Bs[L][e * 64 + j];
        float a2[8];
        #pragma unroll
        for (int s = 0; s < 8; ++s) a2[s] = bb;
        for (int k = 0; k < 64; ++k) {
            float w = W[k * 64 + j];
            #pragma unroll
            for (int s = 0; s < 8; ++s)
                a2[s] = fmaf(hin[(s0 + s) * 64 + k], w, a2[s]);
        }
        #pragma unroll
        for (int s = 0; s < 8; ++s) hout[(s0 + s) * 64 + j] = fmaxf(a2[s], 0.f);
        __syncthreads();
        float* t = hin; hin = hout; hout = t;
    }

    if (j < NA) {
        const float* W6e = W6 + (size_t)e * 64 * NA;
        float b6 = B6[e * NA + j];
        int send = min(n, s0 + 8);
        for (int s = s0; s < send; ++s) {
            float a = b6;
            #pragma unroll
            for (int k = 0; k < 64; ++k)
                a = fmaf(hin[s * 64 + k], W6e[k * NA + j], a);
            out[(size_t)sid[s] * NA + j] = a;
        }
    }
}

// ---------------- launch ----------------
extern "C" void kernel_launch(void* const* d_in, const int* in_sizes, int n_in,
                              void* d_out, int out_size) {
    const float* state = (const float*)d_in[0];
    const int*   rm    = (const int*)d_in[1];
    const float* k1 = (const float*)d_in[2];
    const float* c1 = (const float*)d_in[3];
    const float* k2 = (const float*)d_in[4];
    const float* c2 = (const float*)d_in[5];
    const float* k3 = (const float*)d_in[6];
    const float* c3 = (const float*)d_in[7];
    const float* W1 = (const float*)d_in[8];
    const float* B1 = (const float*)d_in[9];
    const float* W2 = (const float*)d_in[10];
    const float* B2 = (const float*)d_in[11];
    const float* W3 = (const float*)d_in[12];
    const float* B3 = (const float*)d_in[13];
    const float* W4 = (const float*)d_in[14];
    const float* B4 = (const float*)d_in[15];
    const float* W5 = (const float*)d_in[16];
    const float* B5 = (const float*)d_in[17];
    const float* W6 = (const float*)d_in[18];
    const float* B6 = (const float*)d_in[19];
    float* out = (float*)d_out;

    int nB = in_sizes[1];
    if (nB > NB_MAX) nB = NB_MAX;

    int M1 = nB * 400, M2 = nB * 81, M3 = nB * 49;

    prep_kernel<<<1024, 256>>>(state, k1, k2, k3, W1, nB);
    assign_kernel<<<1, 256>>>(rm, nB);
    conv_mma_kernel<1><<<(M1 + 255) / 256, 256>>>(c1, M1);
    conv_mma_kernel<2><<<(M2 + 127) / 128, 256>>>(c2, M2);
    conv_mma_kernel<3><<<(M3 + 127) / 128, 256>>>(c3, M3);
    mlp1_kernel<<<dim3(NE, (nB + 127) / 128), 256>>>(B1);
    mlp2_kernel<<<dim3(NE, (nB + TB - 1) / TB), 256>>>(
        W2, B2, W3, B3, W4, B4, W5, B5, W6, B6, out);
}

// round 16
// speedup vs baseline: 1.6401x; 1.1600x over previous
#include <cuda_runtime.h>
#include <cuda_bf16.h>
#include <cstdint>

// ---------------- problem constants ----------------
#define NB_MAX   2048
#define NE       8
#define NA       6
#define TB       32

// ---------------- scratch (device globals; no allocs allowed) ----------------
// All activations stored as uint2 {bf16x2_hi, bf16x2_lo} pairs.
__device__ uint2 g_x0[(size_t)NB_MAX * 3 * 84 * 42];   // [b][c][h][w/2]
// x1/x2/x3 declared as uint4 for guaranteed 16B alignment (accessed as uint2/uint4)
__device__ uint4 g_x1r[(size_t)NB_MAX * 400 * 8];
__device__ uint4 g_x2r[(size_t)NB_MAX * 81 * 16];
__device__ uint4 g_x3r[(size_t)NB_MAX * 49 * 16];
#define g_x1 ((uint2*)g_x1r)
#define g_x2 ((uint2*)g_x2r)
#define g_x3 ((uint2*)g_x3r)
__device__ float g_h1[(size_t)NB_MAX * 64];
__device__ int   g_cnt[NE];
__device__ int   g_idx[NE * NB_MAX];
// conv weights as MMA B-fragments: [chunk][k16][col][q] = {bh0,bh1,bl0,bl1}
// B1f: plain k-order. B2f/B3f/W1f: PERMUTED k-order (word q = logical elems base+4q..+3)
__device__ uint4 g_B1f[3 * 512];
__device__ uint4 g_B2f[8 * 1024];
__device__ uint4 g_B3f[9 * 1024];
__device__ uint4 g_W1f[NE * 196 * 256];

// ---------------- mma.sync helper ----------------
__device__ __forceinline__ void mma_bf16(float* c, uint32_t a0, uint32_t a1,
                                         uint32_t a2, uint32_t a3,
                                         uint32_t b0, uint32_t b1) {
    asm volatile(
        "mma.sync.aligned.m16n8k16.row.col.f32.bf16.bf16.f32 "
        "{%0,%1,%2,%3}, {%4,%5,%6,%7}, {%8,%9}, {%0,%1,%2,%3};"
        : "+f"(c[0]), "+f"(c[1]), "+f"(c[2]), "+f"(c[3])
        : "r"(a0), "r"(a1), "r"(a2), "r"(a3), "r"(b0), "r"(b1));
}

// ---------------- bf16 hi/lo packing ----------------
__device__ __forceinline__ void packpair(float a, float b, unsigned& h, unsigned& l) {
    __nv_bfloat162 hh = __floats2bfloat162_rn(a, b);
    float ra = a - __bfloat162float(__low2bfloat16(hh));
    float rb = b - __bfloat162float(__high2bfloat16(hh));
    __nv_bfloat162 ll = __floats2bfloat162_rn(ra, rb);
    h = *(unsigned*)&hh; l = *(unsigned*)&ll;
}

// ---------------- weight prepack + input split ----------------
__global__ void prep_kernel(const float* __restrict__ state,
                            const float* __restrict__ k1, const float* __restrict__ k2,
                            const float* __restrict__ k3, const float* __restrict__ W1,
                            int nB) {
    int t0 = blockIdx.x * blockDim.x + threadIdx.x;
    int stride = gridDim.x * blockDim.x;
    // conv1 input: one thread handles all 3 channels of a pixel pair (single sweep)
    int nx0 = nB * 3528;
    for (int i = t0; i < nx0; i += stride) {
        int b = i / 3528, rem = i % 3528;
        int h = rem / 42, wp = rem % 42;
        int base = ((b * 84 + h) * 84 + wp * 2) * 3;
        #pragma unroll
        for (int c = 0; c < 3; ++c) {
            unsigned hh, ll;
            packpair(state[base + c], state[base + 3 + c], hh, ll);
            g_x0[b * 10584 + c * 3528 + h * 42 + wp] = make_uint2(hh, ll);
        }
    }
    // conv1 B (plain order): kk = c*64 + kh*8 + kw
    for (int t = t0; t < 3 * 512; t += stride) {
        int ch = t / 512, rem = t % 512;
        int k16 = rem >> 7, col = (rem >> 2) & 31, q = rem & 3;
        int kb = ch * 64 + k16 * 16 + 2 * q;
        const float* w = k1 + col * 192;
        uint4 f;
        packpair(w[kb],     w[kb + 1], f.x, f.z);
        packpair(w[kb + 8], w[kb + 9], f.y, f.w);
        g_B1f[t] = f;
    }
    // conv2 B (PERMUTED): word q covers logical elems base+4q..+3; kk = tap*32 + c
    for (int t = t0; t < 8 * 1024; t += stride) {
        int ch = t >> 10, rem = t & 1023;
        int k16 = rem >> 8, col = (rem >> 2) & 63, q = rem & 3;
        int kb = ch * 64 + k16 * 16 + 4 * q;
        const float* w = k2 + col * 512;
        auto W2f = [&](int kk) { int tap = kk >> 5, c = kk & 31; return w[c * 16 + tap]; };
        uint4 f;
        packpair(W2f(kb),     W2f(kb + 1), f.x, f.z);
        packpair(W2f(kb + 2), W2f(kb + 3), f.y, f.w);
        g_B2f[t] = f;
    }
    // conv3 B (PERMUTED): kk = tap*64 + c
    for (int t = t0; t < 9 * 1024; t += stride) {
        int ch = t >> 10, rem = t & 1023;
        int k16 = rem >> 8, col = (rem >> 2) & 63, q = rem & 3;
        int kb = ch * 64 + k16 * 16 + 4 * q;
        const float* w = k3 + col * 576;
        auto W3f = [&](int kk) { int tap = kk >> 6, c = kk & 63; return w[c * 9 + tap]; };
        uint4 f;
        packpair(W3f(kb),     W3f(kb + 1), f.x, f.z);
        packpair(W3f(kb + 2), W3f(kb + 3), f.y, f.w);
        g_B3f[t] = f;
    }
    // W1 fragments (PERMUTED), col-innermost for coalesced W1 reads.
    for (int t = t0; t < NE * 196 * 256; t += stride) {
        int col = t & 63, q = (t >> 6) & 3;
        int rest = t >> 8;
        int k16 = rest % 196, e = rest / 196;
        int kb = k16 * 16 + 4 * q;
        const float* We = W1 + (size_t)e * 200704;
        auto W1v = [&](int kk) { int p = kk >> 6, c = kk & 63; return We[(c * 49 + p) * 64 + col]; };
        uint4 f;
        packpair(W1v(kb),     W1v(kb + 1), f.x, f.z);
        packpair(W1v(kb + 2), W1v(kb + 3), f.y, f.w);
        g_W1f[((e * 196 + k16) * 64 + col) * 4 + q] = f;
    }
}

// ---------------- expert bucketing ----------------
__global__ void assign_kernel(const int* __restrict__ rm32, int n) {
    __shared__ int s_is64;
    int tid = threadIdx.x;
    if (tid == 0) s_is64 = 1;
    __syncthreads();
    for (int i = tid; i < 256; i += blockDim.x)
        if (rm32[2*i + 1] != 0) atomicExch(&s_is64, 0);
    if (tid < NE) g_cnt[tid] = 0;
    __syncthreads();
    int is64 = s_is64;
    const long long* rm64 = (const long long*)rm32;
    for (int b = tid; b < n; b += blockDim.x) {
        int e = is64 ? (int)rm64[b] : rm32[b];
        int pos = atomicAdd(&g_cnt[e], 1);
        g_idx[e * NB_MAX + pos] = b;
    }
}

// ---------------- conv-as-GEMM: TM=1 per warp, 256 threads -----------------
// conv1 (N=32): 8 M-warps x 16 rows = 128 rows/block, plain k-order.
// conv2/3 (N=64): 4 M-warps x 2 N-halves, 64 rows/block, PERMUTED k-order.
template<int CONV>
__global__ void __launch_bounds__(256) conv_mma_kernel(
    const float* __restrict__ bias, int MTOT) {
    constexpr int KCH  = (CONV == 1) ? 3 : ((CONV == 2) ? 8 : 9);
    constexpr int N    = (CONV == 1) ? 32 : 64;
    constexpr int POS  = (CONV == 1) ? 400 : ((CONV == 2) ? 81 : 49);
    constexpr int OW   = (CONV == 1) ? 20 : ((CONV == 2) ? 9 : 7);
    constexpr int NT   = 4;
    constexpr int ROWS = (CONV == 1) ? 128 : 64;
    constexpr int BCH  = N * 16;

    const uint4* __restrict__ gB = (CONV == 1) ? g_B1f : ((CONV == 2) ? g_B2f : g_B3f);
    const uint2* __restrict__ X  = (CONV == 1) ? g_x0 : ((CONV == 2) ? g_x1 : g_x2);

    int tid = threadIdx.x, wid = tid >> 5, lane = tid & 31;
    int mw = (CONV == 1) ? wid : (wid >> 1);
    int nh = (CONV == 1) ? 0   : (wid & 1);
    int kp = lane & 3, klo = kp * 2;
    int tb = blockIdx.x * ROWS;

    int orow[2];
    int pb[2];               // pair-unit row base
    #pragma unroll
    for (int i = 0; i < 2; ++i) {
        int gr = tb + mw * 16 + i * 8 + (lane >> 2);
        orow[i] = gr;
        if (gr >= MTOT) gr = MTOT - 1;
        int b = gr / POS, p = gr % POS;
        int oh = p / OW, ow = p % OW;
        if (CONV == 1)      pb[i] = b * 10584 + oh * 168 + ow * 2;
        else if (CONV == 2) pb[i] = b * 6400  + oh * 640 + ow * 32;
        else                pb[i] = b * 2592  + oh * 288 + ow * 32;
    }

    float C[NT][4];
    #pragma unroll
    for (int nt = 0; nt < NT; ++nt)
        #pragma unroll
        for (int q = 0; q < 4; ++q) C[nt][q] = 0.f;

    #pragma unroll 1
    for (int ch = 0; ch < KCH; ++ch) {
        int cb1 = 0;
        if (CONV == 1)      cb1 = ch * 3528;
        else if (CONV == 3) { int kh = ch / 3, kw = ch % 3; cb1 = kh * 288 + kw * 32; }

        #pragma unroll
        for (int k16 = 0; k16 < 4; ++k16) {
            uint32_t ah[4], al[4];
            if (CONV == 1) {
                int o0 = cb1 + k16 * 84 + kp;
                int o1 = o0 + 42;
                uint2 u00 = X[pb[0] + o0];
                uint2 u10 = X[pb[1] + o0];
                uint2 u01 = X[pb[0] + o1];
                uint2 u11 = X[pb[1] + o1];
                ah[0] = u00.x; ah[1] = u10.x; ah[2] = u01.x; ah[3] = u11.x;
                al[0] = u00.y; al[1] = u10.y; al[2] = u01.y; al[3] = u11.y;
            } else {
                int o;
                if (CONV == 2) {
                    int tap = ch * 2 + (k16 >> 1);
                    int kh = tap >> 2, kw = tap & 3;
                    o = kh * 320 + kw * 16 + (k16 & 1) * 8 + kp * 2;
                } else {
                    o = cb1 + k16 * 8 + kp * 2;
                }
                uint4 v0 = *(const uint4*)(X + pb[0] + o);
                uint4 v1 = *(const uint4*)(X + pb[1] + o);
                ah[0] = v0.x; ah[1] = v1.x; ah[2] = v0.z; ah[3] = v1.z;
                al[0] = v0.y; al[1] = v1.y; al[2] = v0.w; al[3] = v1.w;
            }
            const uint4* bk = gB + ch * BCH + k16 * (N * 4) + nh * 128
                              + (lane >> 2) * 4 + (lane & 3);
            #pragma unroll
            for (int nt = 0; nt < NT; ++nt) {
                uint4 f = bk[nt * 32];
                mma_bf16(C[nt], ah[0], ah[1], ah[2], ah[3], f.x, f.y);
                mma_bf16(C[nt], ah[0], ah[1], ah[2], ah[3], f.z, f.w);
                mma_bf16(C[nt], al[0], al[1], al[2], al[3], f.x, f.y);
            }
        }
    }

    // ---- epilogue: bias + relu; fused {hi,lo} STG.64 ----
    #pragma unroll
    for (int nt = 0; nt < NT; ++nt) {
        int col = nh * 32 + nt * 8 + klo;
        float2 bv = *(const float2*)(bias + col);
        #pragma unroll
        for (int h = 0; h < 2; ++h) {
            int rw = orow[h];
            if (rw >= MTOT) continue;
            float v0 = fmaxf(C[nt][h*2]     + bv.x, 0.f);
            float v1 = fmaxf(C[nt][h*2 + 1] + bv.y, 0.f);
            unsigned hh, ll;
            packpair(v0, v1, hh, ll);
            int cp = nh * 16 + nt * 4 + kp;
            if (CONV == 1)      g_x1[(size_t)rw * 16 + cp] = make_uint2(hh, ll);
            else if (CONV == 2) g_x2[(size_t)rw * 32 + cp] = make_uint2(hh, ll);
            else                g_x3[(size_t)rw * 32 + cp] = make_uint2(hh, ll);
        }
    }
}

// ---------------- MLP layer 1 on HMMA: TM=1, 64 rows/block (PERMUTED) ------
__global__ void __launch_bounds__(256) mlp1_kernel(const float* __restrict__ B1) {
    int e = blockIdx.x;
    int cnt = g_cnt[e];
    int base = blockIdx.y * 64;
    if (base >= cnt) return;

    int tid = threadIdx.x, wid = tid >> 5, lane = tid & 31;
    int mw = wid >> 1, nh = wid & 1;
    int kp = lane & 3, klo = kp * 2;

    int sidr[2]; int orow[2];
    #pragma unroll
    for (int i = 0; i < 2; ++i) {
        int idx = base + mw * 16 + i * 8 + (lane >> 2);
        orow[i] = idx;
        int cidx = (idx < cnt) ? idx : cnt - 1;
        sidr[i] = g_idx[e * NB_MAX + cidx] * 1568;   // pair units
    }

    float C[4][4];
    #pragma unroll
    for (int nt = 0; nt < 4; ++nt)
        #pragma unroll
        for (int q = 0; q < 4; ++q) C[nt][q] = 0.f;

    const uint4* gW = g_W1f + e * 196 * 256 + nh * 128 + (lane >> 2) * 4 + (lane & 3);

    #pragma unroll 4
    for (int k16 = 0; k16 < 196; ++k16) {
        int o = k16 * 8 + kp * 2;
        uint4 v0 = *(const uint4*)(g_x3 + sidr[0] + o);
        uint4 v1 = *(const uint4*)(g_x3 + sidr[1] + o);
        uint32_t ah[4], al[4];
        ah[0] = v0.x; ah[1] = v1.x; ah[2] = v0.z; ah[3] = v1.z;
        al[0] = v0.y; al[1] = v1.y; al[2] = v0.w; al[3] = v1.w;
        const uint4* bk = gW + k16 * 256;
        #pragma unroll
        for (int nt = 0; nt < 4; ++nt) {
            uint4 f = bk[nt * 32];
            mma_bf16(C[nt], ah[0], ah[1], ah[2], ah[3], f.x, f.y);
            mma_bf16(C[nt], ah[0], ah[1], ah[2], ah[3], f.z, f.w);
            mma_bf16(C[nt], al[0], al[1], al[2], al[3], f.x, f.y);
        }
    }

    #pragma unroll
    for (int nt = 0; nt < 4; ++nt) {
        int col = nh * 32 + nt * 8 + klo;
        float2 bv = *(const float2*)(B1 + e * 64 + col);
        #pragma unroll
        for (int h = 0; h < 2; ++h) {
            int idx = orow[h];
            if (idx >= cnt) continue;
            int sid = g_idx[e * NB_MAX + idx];
            float2 o2;
            o2.x = fmaxf(C[nt][h*2]     + bv.x, 0.f);
            o2.y = fmaxf(C[nt][h*2 + 1] + bv.y, 0.f);
            *(float2*)(g_h1 + (size_t)sid * 64 + col) = o2;
        }
    }
}

// ---------------- MLP layers 2-6 ----------------
__global__ void __launch_bounds__(256) mlp2_kernel(
    const float* __restrict__ W2, const float* __restrict__ B2,
    const float* __restrict__ W3, const float* __restrict__ B3,
    const float* __restrict__ W4, const float* __restrict__ B4,
    const float* __restrict__ W5, const float* __restrict__ B5,
    const float* __restrict__ W6, const float* __restrict__ B6,
    float* __restrict__ out) {
    int e = blockIdx.x;
    int base = blockIdx.y * TB;
    int n = g_cnt[e] - base;
    if (n <= 0) return;
    if (n > TB) n = TB;

    __shared__ float hA[TB * 64], hB[TB * 64];
    __shared__ int   sid[TB];
    int tid = threadIdx.x, j = tid & 63, sq = tid >> 6;
    int s0 = sq * 8;

    if (tid < TB) sid[tid] = (tid < n) ? g_idx[e * NB_MAX + base + tid] : -1;
    __syncthreads();

    for (int i = tid; i < TB * 64; i += 256) {
        int s = i >> 6, d = i & 63;
        int bb = sid[s];
        hA[i] = (bb >= 0) ? g_h1[(size_t)bb * 64 + d] : 0.f;
    }
    __syncthreads();

    const float* Ws[4] = {W2, W3, W4, W5};
    const float* Bs[4] = {B2, B3, B4, B5};
    float* hin = hA;
    float* hout = hB;
    #pragma unroll 1
    for (int L = 0; L < 4; ++L) {
        const float* W = Ws[L] + (size_t)e * 4096;
        float bb = Bs[L][e * 64 + j];
        float a2[8];
        #pragma unroll
        for (int s = 0; s < 8; ++s) a2[s] = bb;
        for (int k = 0; k < 64; ++k) {
            float w = W[k * 64 + j];
            #pragma unroll
            for (int s = 0; s < 8; ++s)
                a2[s] = fmaf(hin[(s0 + s) * 64 + k], w, a2[s]);
        }
        #pragma unroll
        for (int s = 0; s < 8; ++s) hout[(s0 + s) * 64 + j] = fmaxf(a2[s], 0.f);
        __syncthreads();
        float* t = hin; hin = hout; hout = t;
    }

    if (j < NA) {
        const float* W6e = W6 + (size_t)e * 64 * NA;
        float b6 = B6[e * NA + j];
        int send = min(n, s0 + 8);
        for (int s = s0; s < send; ++s) {
            float a = b6;
            #pragma unroll
            for (int k = 0; k < 64; ++k)
                a = fmaf(hin[s * 64 + k], W6e[k * NA + j], a);
            out[(size_t)sid[s] * NA + j] = a;
        }
    }
}

// ---------------- launch ----------------
extern "C" void kernel_launch(void* const* d_in, const int* in_sizes, int n_in,
                              void* d_out, int out_size) {
    const float* state = (const float*)d_in[0];
    const int*   rm    = (const int*)d_in[1];
    const float* k1 = (const float*)d_in[2];
    const float* c1 = (const float*)d_in[3];
    const float* k2 = (const float*)d_in[4];
    const float* c2 = (const float*)d_in[5];
    const float* k3 = (const float*)d_in[6];
    const float* c3 = (const float*)d_in[7];
    const float* W1 = (const float*)d_in[8];
    const float* B1 = (const float*)d_in[9];
    const float* W2 = (const float*)d_in[10];
    const float* B2 = (const float*)d_in[11];
    const float* W3 = (const float*)d_in[12];
    const float* B3 = (const float*)d_in[13];
    const float* W4 = (const float*)d_in[14];
    const float* B4 = (const float*)d_in[15];
    const float* W5 = (const float*)d_in[16];
    const float* B5 = (const float*)d_in[17];
    const float* W6 = (const float*)d_in[18];
    const float* B6 = (const float*)d_in[19];
    float* out = (float*)d_out;

    int nB = in_sizes[1];
    if (nB > NB_MAX) nB = NB_MAX;

    int M1 = nB * 400, M2 = nB * 81, M3 = nB * 49;

    prep_kernel<<<1024, 256>>>(state, k1, k2, k3, W1, nB);
    assign_kernel<<<1, 256>>>(rm, nB);
    conv_mma_kernel<1><<<(M1 + 127) / 128, 256>>>(c1, M1);
    conv_mma_kernel<2><<<(M2 + 63) / 64, 256>>>(c2, M2);
    conv_mma_kernel<3><<<(M3 + 63) / 64, 256>>>(c3, M3);
    mlp1_kernel<<<dim3(NE, (nB + 63) / 64), 256>>>(B1);
    mlp2_kernel<<<dim3(NE, (nB + TB - 1) / TB), 256>>>(
        W2, B2, W3, B3, W4, B4, W5, B5, W6, B6, out);
}